// round 11
// baseline (speedup 1.0000x reference)
#include <cuda_runtime.h>
#include <cstdint>

// B=16, H=128, W=128, C=256, P=8192
//   in_tensor: (B,H,W,C) f32   indices: (B,P,2) f32 (dim0->H, dim1->W)
//   out: (B,P,C) f32
//
// Bilinear: out = p1*(1-mx)(1-my) + p2*mx(1-my) + p3*(1-mx)my + p4*mx*my
//
// R10 findings: coupled producer (tid0 after __syncthreads) self-throttles the
// TMA ring; DRAM stuck at 70%. This version: dedicated producer warp with
// full/empty mbarrier pairs (free-runs up to 5 stages ahead), 8 producer lanes
// issuing one 1KB cp.async.bulk each, consumers signal empty with one arrive
// per warp. Ring: 5 stages x 8KB = 40KB (static smem limit) -> 5 CTAs/SM,
// ~200KB outstanding TMA bytes per SM.

#define GB 16
#define GH 128
#define GW 128
#define GC 256
#define GP 8192

#define NTHREADS 160            // warps 0-3: consumers, warp 4: producer
#define PPC 32                  // points per CTA (same batch: 32 | 8192)
#define STAGES 5
#define PTS_PER_STAGE 2
#define NITER (PPC / PTS_PER_STAGE)            // 16
#define ROW_BYTES (GC * 4)                     // 1024
#define STAGE_BYTES (PTS_PER_STAGE * 4 * ROW_BYTES)  // 8192

__device__ __forceinline__ uint32_t smem_u32(const void* p) {
    uint32_t a;
    asm("{ .reg .u64 t; cvta.to.shared.u64 t, %1; cvt.u32.u64 %0, t; }"
        : "=r"(a) : "l"(p));
    return a;
}

__device__ __forceinline__ void mbar_init(uint32_t bar, uint32_t count) {
    asm volatile("mbarrier.init.shared.b64 [%0], %1;" :: "r"(bar), "r"(count) : "memory");
}

__device__ __forceinline__ void mbar_arrive(uint32_t bar) {
    asm volatile("mbarrier.arrive.shared.b64 _, [%0];" :: "r"(bar) : "memory");
}

__device__ __forceinline__ void mbar_expect_tx(uint32_t bar, uint32_t bytes) {
    asm volatile("mbarrier.arrive.expect_tx.shared.b64 _, [%0], %1;"
                 :: "r"(bar), "r"(bytes) : "memory");
}

__device__ __forceinline__ void bulk_g2s(uint32_t dst, const void* src,
                                         uint32_t bytes, uint32_t bar) {
    asm volatile(
        "cp.async.bulk.shared::cta.global.mbarrier::complete_tx::bytes "
        "[%0], [%1], %2, [%3];"
        :: "r"(dst), "l"(src), "r"(bytes), "r"(bar) : "memory");
}

__device__ __forceinline__ void mbar_wait(uint32_t bar, uint32_t parity) {
    asm volatile(
        "{\n\t"
        ".reg .pred P;\n\t"
        "WAIT_%=:\n\t"
        "mbarrier.try_wait.parity.acquire.cta.shared::cta.b64 P, [%0], %1, 0x989680;\n\t"
        "@P bra DONE_%=;\n\t"
        "bra WAIT_%=;\n\t"
        "DONE_%=:\n\t"
        "}"
        :: "r"(bar), "r"(parity) : "memory");
}

__global__ __launch_bounds__(NTHREADS) void grid_sample_tma(
    const float* __restrict__ in_tensor,
    const float* __restrict__ indices,
    float* __restrict__ out)
{
    __shared__ alignas(16) unsigned char stage_buf[STAGES * STAGE_BYTES];
    __shared__ alignas(8)  unsigned long long full_bar[STAGES];
    __shared__ alignas(8)  unsigned long long empty_bar[STAGES];
    __shared__ float2 sidx[PPC];

    const int tid    = threadIdx.x;
    const int cta    = blockIdx.x;
    const int point0 = cta * PPC;
    const int b      = point0 >> 13;               // batch (constant per CTA)

    if (tid < PPC)
        sidx[tid] = __ldg(((const float2*)indices) + point0 + tid);

    const uint32_t fbar0 = smem_u32(&full_bar[0]);
    const uint32_t ebar0 = smem_u32(&empty_bar[0]);
    const uint32_t sbuf0 = smem_u32(&stage_buf[0]);

    if (tid == 0) {
        #pragma unroll
        for (int s = 0; s < STAGES; s++) {
            mbar_init(fbar0 + s * 8, 1);   // 1 arrive: producer's expect_tx
            mbar_init(ebar0 + s * 8, 4);   // 4 arrives: one per consumer warp
        }
    }
    __syncthreads();   // barriers + sidx visible

    const char* img = (const char*)in_tensor + (size_t)b * (GH * GW) * ROW_BYTES;

    if (tid >= 128) {
        // ── Producer warp ──────────────────────────────────────────────
        const int t = tid - 128;
        if (t < 8) {
            const int pk     = t >> 2;    // point within stage (0/1)
            const int corner = t & 3;     // which of the 4 corner rows
            int stage = 0, phase = 1;     // phase=1: first empty-wait passes
            for (int it = 0; it < NITER; it++) {
                const uint32_t eb = ebar0 + stage * 8;
                const uint32_t fb = fbar0 + stage * 8;
                mbar_wait(eb, phase);
                if (t == 0) mbar_expect_tx(fb, STAGE_BYTES);
                __syncwarp(0x000000FFu);  // expect_tx posted before copies
                const float2 ind = sidx[it * PTS_PER_STAGE + pk];
                const float fx = floorf(ind.x);
                const float fy = floorf(ind.y);
                const int row  = (int)fx * GW + (int)fy;
                // ceil==floor when coord integral (weight 0) -> delta 0 exact
                const int dh = (ind.x > fx) ? (GW * ROW_BYTES) : 0;
                const int dw = (ind.y > fy) ? ROW_BYTES : 0;
                const int off = (corner & 1 ? dh : 0) + (corner & 2 ? dw : 0);
                bulk_g2s(sbuf0 + stage * STAGE_BYTES + (pk * 4 + corner) * ROW_BYTES,
                         img + (size_t)row * ROW_BYTES + off, ROW_BYTES, fb);
                if (++stage == STAGES) { stage = 0; phase ^= 1; }
            }
        }
    } else {
        // ── Consumer warps (128 threads, 64 per point) ────────────────
        const int k    = tid >> 6;        // point within stage (0/1)
        const int slot = tid & 63;        // float4 slot in C=256 row
        const int lane = tid & 31;
        float4* out4 = (float4*)out;

        int stage = 0, phase = 0;
        for (int it = 0; it < NITER; it++) {
            const uint32_t fb = fbar0 + stage * 8;
            const uint32_t eb = ebar0 + stage * 8;
            mbar_wait(fb, phase);

            const int p = it * PTS_PER_STAGE + k;
            const float2 ind = sidx[p];
            const float mx = ind.x - floorf(ind.x);
            const float my = ind.y - floorf(ind.y);
            const float omx = 1.0f - mx;
            const float omy = 1.0f - my;
            const float w1 = omx * omy;
            const float w2 = mx  * omy;
            const float w3 = omx * my;
            const float w4 = mx  * my;

            const float4* sb = (const float4*)(stage_buf + stage * STAGE_BYTES
                                               + k * 4 * ROW_BYTES);
            const float4 v1 = sb[slot];
            const float4 v2 = sb[64 + slot];
            const float4 v3 = sb[128 + slot];
            const float4 v4 = sb[192 + slot];

            float4 o;
            o.x = v1.x * w1 + v2.x * w2 + v3.x * w3 + v4.x * w4;
            o.y = v1.y * w1 + v2.y * w2 + v3.y * w3 + v4.y * w4;
            o.z = v1.z * w1 + v2.z * w2 + v3.z * w3 + v4.z * w4;
            o.w = v1.w * w1 + v2.w * w2 + v3.w * w3 + v4.w * w4;

            __stcs(out4 + (size_t)(point0 + p) * (GC / 4) + slot, o);

            __syncwarp();                 // all lanes done reading stage
            if (lane == 0) mbar_arrive(eb);

            if (++stage == STAGES) { stage = 0; phase ^= 1; }
        }
    }
}

extern "C" void kernel_launch(void* const* d_in, const int* in_sizes, int n_in,
                              void* d_out, int out_size)
{
    const float* in_tensor = (const float*)d_in[0];
    const float* indices   = (const float*)d_in[1];
    float*       out       = (float*)d_out;

    const int blocks = (GB * GP) / PPC;   // 4096
    grid_sample_tma<<<blocks, NTHREADS>>>(in_tensor, indices, out);
}